// round 13
// baseline (speedup 1.0000x reference)
#include <cuda_runtime.h>
#include <cuda_bf16.h>
#include <math.h>

// LSTM: T=512, B=64, I=H=512.  out[t,b,h] = h_t.
// conv_a/conv_w: split-bf16 fragments (R8, unchanged).
// lstm_rec (640 thr): warps 0-15 = persistent HMMA recurrence;
//   warps 16-19 = in-CTA GEMM sub-unit producing x_proj tiles in t-order.
// R13 fix vs R12: removed the t+7 lookahead (it only proved ONE of the four
//   tile-owner groups finished -> early-step corruption). tid0 now always
//   acquire-probes g_td[t] itself; probe latency hidden under the cnt poll.

#define Tq 512
#define Bq 64
#define Hq 512
#define G4 2048
#define AF4 2097152u
#define WF2 262144u

typedef unsigned long long ull;

__device__ float g_xp[(size_t)Tq * G4 * Bq];        // x_proj scratch (no bias)
__device__ unsigned g_cnt[4 * 32];                  // per-group step counters
__device__ unsigned g_td[Tq];                       // per-t x_proj progress (4096 = done)
__device__ unsigned g_fin;                          // global finish counter
__device__ uint4 g_af[2 * AF4];                     // A frags hi|lo
__device__ uint2 g_wf[2 * WF2];                     // W_ih frags hi|lo
__device__ uint4 g_hf[2 * 8192];                    // h frags [par][hi|lo][bq][kc][lane]

__device__ __forceinline__ void cpa16(void* s, const void* g) {
    unsigned sa = (unsigned)__cvta_generic_to_shared(s);
    asm volatile("cp.async.cg.shared.global [%0], [%1], 16;" :: "r"(sa), "l"(g));
}
__device__ __forceinline__ void cpcommit() { asm volatile("cp.async.commit_group;"); }
template <int N> __device__ __forceinline__ void cpwait() {
    asm volatile("cp.async.wait_group %0;" :: "n"(N));
}
__device__ __forceinline__ float sigf(float x) {
    return __fdividef(1.f, 1.f + __expf(-x));
}
__device__ __forceinline__ float tanhx(float x) {
    return __fdividef(2.f, 1.f + __expf(-2.f * x)) - 1.f;
}
__device__ __forceinline__ void split2(float2 v, unsigned& hi, unsigned& lo) {
    __nv_bfloat16 hx = __float2bfloat16(v.x);
    __nv_bfloat16 hy = __float2bfloat16(v.y);
    __nv_bfloat16 lx = __float2bfloat16(v.x - __bfloat162float(hx));
    __nv_bfloat16 ly = __float2bfloat16(v.y - __bfloat162float(hy));
    hi = (unsigned)__bfloat16_as_ushort(hx) | ((unsigned)__bfloat16_as_ushort(hy) << 16);
    lo = (unsigned)__bfloat16_as_ushort(lx) | ((unsigned)__bfloat16_as_ushort(ly) << 16);
}
__device__ __forceinline__ void mma16816(float* c, uint4 a, unsigned b0, unsigned b1) {
    asm volatile(
        "mma.sync.aligned.m16n8k16.row.col.f32.bf16.bf16.f32 "
        "{%0,%1,%2,%3},{%4,%5,%6,%7},{%8,%9},{%0,%1,%2,%3};"
        : "+f"(c[0]), "+f"(c[1]), "+f"(c[2]), "+f"(c[3])
        : "r"(a.x), "r"(a.y), "r"(a.z), "r"(a.w), "r"(b0), "r"(b1));
}

__global__ __launch_bounds__(256) void conv_a(const float* __restrict__ x) {
    unsigned idx = blockIdx.x * 256 + threadIdx.x;
    int lane = idx & 31;
    int kc = (idx >> 5) & 31;
    int mf = idx >> 10;
    int gr = lane >> 2, tc = (lane & 3) * 2;
    const float* base = x + (size_t)(mf * 16 + gr) * 512 + kc * 16 + tc;
    float2 r0 = *(const float2*)(base);
    float2 r1 = *(const float2*)(base + 8);
    float2 r2 = *(const float2*)(base + 8 * 512);
    float2 r3 = *(const float2*)(base + 8 * 512 + 8);
    uint4 hi, lo;
    split2(r0, hi.x, lo.x);
    split2(r2, hi.y, lo.y);
    split2(r1, hi.z, lo.z);
    split2(r3, hi.w, lo.w);
    unsigned o = (mf * 32 + kc) * 32 + lane;
    g_af[o] = hi;
    g_af[o + AF4] = lo;
}

__global__ __launch_bounds__(256) void conv_w(const float* __restrict__ W) {
    unsigned idx = blockIdx.x * 256 + threadIdx.x;
    int lane = idx & 31;
    int kc = (idx >> 5) & 31;
    int nf = idx >> 10;
    int gr = lane >> 2, tc = (lane & 3) * 2;
    const float* base = W + (size_t)(nf * 8 + gr) * 512 + kc * 16 + tc;
    float2 r0 = *(const float2*)(base);
    float2 r1 = *(const float2*)(base + 8);
    uint2 hi, lo;
    split2(r0, hi.x, lo.x);
    split2(r1, hi.y, lo.y);
    unsigned o = (nf * 32 + kc) * 32 + lane;
    g_wf[o] = hi;
    g_wf[o + WF2] = lo;
}

// ---------------------------------------------------------------------------
// smem layout
// ---------------------------------------------------------------------------
#define OFF_WF_LO 65536
#define OFF_HF    131072
#define OFF_HF_LO 147456
#define OFF_PEX   163840      // [32 rows][68] f32 = 8704
#define OFF_HO    172544      // [16][16] f32 = 1024
#define OFF_HBL   173568      // [16][17] u32 = 1088
#define OFF_BS    174656      // 64 f32 = 256
#define OFF_WS2   174912      // GEMM W double buffer 2x4096
#define REC_SMEM  183104

__global__ __launch_bounds__(640, 1) void lstm_rec(
    const float* __restrict__ Whh, const float* __restrict__ bih,
    const float* __restrict__ bhh, float* __restrict__ out)
{
    extern __shared__ __align__(16) char smc[];
    uint2* wfHI = (uint2*)(smc);
    uint2* wfLO = (uint2*)(smc + OFF_WF_LO);
    uint4* hfHI = (uint4*)(smc + OFF_HF);
    uint4* hfLO = (uint4*)(smc + OFF_HF_LO);
    float* pex = (float*)(smc + OFF_PEX);
    float* ho = (float*)(smc + OFF_HO);
    unsigned* hbl = (unsigned*)(smc + OFF_HBL);
    float* bsm = (float*)(smc + OFF_BS);

    const int tid = threadIdx.x;
    const int bq = blockIdx.x >> 5;
    const int hg = blockIdx.x & 31;
    const int b0 = bq * 16;
    const int hc0 = hg * 16;
    unsigned* cnt = &g_cnt[bq * 32];

    if (tid < 512) {
        // ================= recurrence warps (0..15) =================
        const int warp = tid >> 5;
        const int lane = tid & 31;
        const int eb = tid & 15;
        const int ehcl = (tid >> 4) & 15;
        const int nf = warp & 7;
        const int kh = warp >> 3;

        // build W_hh B-fragments once
        for (int idx = tid; idx < 8192; idx += 512) {
            int l = idx & 31, nfi = (idx >> 5) & 7, kc = idx >> 8;
            int gr = l >> 2, tc2 = (l & 3) * 2;
            int c = nfi * 8 + gr;
            int grow = (c & 3) * 512 + hc0 + (c >> 2);
            const float* wb = Whh + (size_t)grow * 512 + kc * 16 + tc2;
            float2 r0 = *(const float2*)wb;
            float2 r1 = *(const float2*)(wb + 8);
            unsigned h0, l0, h1, l1;
            split2(r0, h0, l0);
            split2(r1, h1, l1);
            wfHI[(kc * 8 + nfi) * 32 + l] = make_uint2(h0, h1);
            wfLO[(kc * 8 + nfi) * 32 + l] = make_uint2(l0, l1);
        }
        if (tid < 64)
            bsm[tid] = bih[(tid & 3) * 512 + hc0 + (tid >> 2)]
                     + bhh[(tid & 3) * 512 + hc0 + (tid >> 2)];
        asm volatile("bar.sync 7, 512;" ::: "memory");

        float cst = 0.f;

#pragma unroll 1
        for (int t = 0; t < Tq; t++) {
            if (tid == 0) {
                // early acquire probe of THIS step's x_proj counter
                unsigned vt;
                asm volatile("ld.acquire.gpu.u32 %0, [%1];"
                             : "=r"(vt) : "l"(&g_td[t]) : "memory");
                if (t > 0) {
                    unsigned tgt = 32u * (unsigned)t;
                    unsigned v;
                    do {
                        asm volatile("ld.acquire.gpu.u32 %0, [%1];"
                                     : "=r"(v) : "l"(cnt) : "memory");
                    } while (v < tgt);
                }
                if (vt < 4096u) {
                    unsigned v;
                    do {
                        asm volatile("ld.acquire.gpu.u32 %0, [%1];"
                                     : "=r"(v) : "l"(&g_td[t]) : "memory");
                    } while (v < 4096u);
                }
            }
            asm volatile("bar.sync 7, 512;" ::: "memory");

            float xv0 = 0.f, xv1 = 0.f, xv2 = 0.f, xv3 = 0.f;
            if (tid < 256) {
                // L2-coherent loads (written by peer CTAs this launch)
                const float* xpt = g_xp + (size_t)t * (G4 * Bq)
                                 + (size_t)(hc0 + ehcl) * Bq + b0 + eb;
                xv0 = __ldcg(xpt + 0 * 512 * Bq);
                xv1 = __ldcg(xpt + 1 * 512 * Bq);
                xv2 = __ldcg(xpt + 2 * 512 * Bq);
                xv3 = __ldcg(xpt + 3 * 512 * Bq);
            }

            if (t > 0) {
                // per-half staging of h A-fragments
                const char* gB = (const char*)g_hf + (size_t)(t & 1) * 131072
                               + bq * 16384 + kh * 8192;
                char* sH = (char*)hfHI + kh * 8192;
                char* sL = (char*)hfLO + kh * 8192;
                int l = tid & 255;
                cpa16(sH + l * 16, gB + l * 16);
                cpa16(sH + (l + 256) * 16, gB + (l + 256) * 16);
                cpa16(sL + l * 16, gB + 65536 + l * 16);
                cpa16(sL + (l + 256) * 16, gB + 65536 + (l + 256) * 16);
                cpcommit();
                cpwait<0>();
                asm volatile("bar.sync %0, 256;" :: "r"(1 + kh) : "memory");

                float cc[4] = { 0.f, 0.f, 0.f, 0.f };
#pragma unroll 4
                for (int kc16 = 0; kc16 < 16; kc16++) {
                    int kc = kh * 16 + kc16;
                    uint4 ah = hfHI[kc * 32 + lane];
                    uint4 al = hfLO[kc * 32 + lane];
                    uint2 wh = wfHI[(kc * 8 + nf) * 32 + lane];
                    uint2 wl = wfLO[(kc * 8 + nf) * 32 + lane];
                    mma16816(cc, ah, wh.x, wh.y);
                    mma16816(cc, al, wh.x, wh.y);
                    mma16816(cc, ah, wl.x, wl.y);
                }
                {
                    int gr = lane >> 2, tc2 = (lane & 3) * 2;
                    int col = nf * 8 + tc2;
                    *(float2*)&pex[(kh * 16 + gr) * 68 + col] = make_float2(cc[0], cc[1]);
                    *(float2*)&pex[(kh * 16 + gr + 8) * 68 + col] = make_float2(cc[2], cc[3]);
                }
                asm volatile("bar.sync 7, 512;" ::: "memory");
            }

            if (tid < 256) {
                float g0 = xv0 + bsm[ehcl * 4 + 0];
                float g1 = xv1 + bsm[ehcl * 4 + 1];
                float g2 = xv2 + bsm[ehcl * 4 + 2];
                float g3 = xv3 + bsm[ehcl * 4 + 3];
                if (t > 0) {
                    float4 p0 = *(const float4*)&pex[eb * 68 + ehcl * 4];
                    float4 p1 = *(const float4*)&pex[(16 + eb) * 68 + ehcl * 4];
                    g0 += p0.x + p1.x;
                    g1 += p0.y + p1.y;
                    g2 += p0.z + p1.z;
                    g3 += p0.w + p1.w;
                }
                float iv = sigf(g0);
                float fv = sigf(g1);
                float gv = tanhx(g2);
                float ov = sigf(g3);
                cst = fv * cst + iv * gv;
                float hv = ov * tanhx(cst);

                ho[eb * 16 + ehcl] = hv;
                {
                    __nv_bfloat16 hh = __float2bfloat16(hv);
                    __nv_bfloat16 hl = __float2bfloat16(hv - __bfloat162float(hh));
                    hbl[ehcl * 17 + eb] = (unsigned)__bfloat16_as_ushort(hh)
                                        | ((unsigned)__bfloat16_as_ushort(hl) << 16);
                }
                asm volatile("bar.sync 10, 256;" ::: "memory");

                if (tid < 32) {
                    if (t < Tq - 1) {
                        int gr = lane >> 2;
                        int k0 = (lane & 3) * 2;
                        unsigned x0 = hbl[k0 * 17 + gr],        x1 = hbl[(k0 + 1) * 17 + gr];
                        unsigned y0 = hbl[k0 * 17 + gr + 8],    y1 = hbl[(k0 + 1) * 17 + gr + 8];
                        unsigned z0 = hbl[(k0 + 8) * 17 + gr],  z1 = hbl[(k0 + 9) * 17 + gr];
                        unsigned w0 = hbl[(k0 + 8) * 17 + gr + 8], w1 = hbl[(k0 + 9) * 17 + gr + 8];
                        uint4 hi = make_uint4(__byte_perm(x0, x1, 0x5410),
                                              __byte_perm(y0, y1, 0x5410),
                                              __byte_perm(z0, z1, 0x5410),
                                              __byte_perm(w0, w1, 0x5410));
                        uint4 lo = make_uint4(__byte_perm(x0, x1, 0x7632),
                                              __byte_perm(y0, y1, 0x7632),
                                              __byte_perm(z0, z1, 0x7632),
                                              __byte_perm(w0, w1, 0x7632));
                        size_t base = (size_t)((t + 1) & 1) * 8192 + (bq * 32 + hg) * 32 + lane;
                        g_hf[base] = hi;
                        g_hf[base + 4096] = lo;
                        __syncwarp();
                        if (lane == 0) {
                            unsigned old;
                            asm volatile("atom.release.gpu.add.u32 %0, [%1], 1;"
                                         : "=r"(old) : "l"(cnt) : "memory");
                        }
                    }
                } else if (tid >= 64 && tid < 128) {
                    int row = (tid - 64) >> 2, f4 = (tid - 64) & 3;
                    float4 v = ((const float4*)(ho + row * 16))[f4];
                    *(float4*)&out[(size_t)t * (Bq * Hq) + (size_t)(b0 + row) * Hq
                                   + hc0 + f4 * 4] = v;
                }
            }
        }

        // global finish: last CTA resets all cross-launch state (replay-safe)
        if (tid == 0) {
            unsigned old;
            asm volatile("atom.release.gpu.add.u32 %0, [%1], 1;"
                         : "=r"(old) : "l"(&g_fin) : "memory");
            if (old == 127u) {
                for (int i = 0; i < Tq; i++) ((volatile unsigned*)g_td)[i] = 0u;
                for (int i = 0; i < 4; i++) ((volatile unsigned*)g_cnt)[i * 32] = 0u;
                *((volatile unsigned*)&g_fin) = 0u;
            }
        }
    } else {
        // ================= GEMM sub-unit (warps 16..19) =================
        const int w = (tid >> 5) - 16;          // 0..3 -> 16 M-rows each
        const int lane = tid & 31;
        const int gr = lane >> 2, tc2 = (lane & 3) * 2;
        const int tid2 = tid - 512;             // 0..127
        char* ws2 = smc + OFF_WS2;

#pragma unroll 1
        for (int j = blockIdx.x; j < Tq * 32; j += 128) {
            int t = j >> 5, ntH = j & 31;

            // stage W for kc 0,1
#pragma unroll
            for (int p = 0; p < 2; p++) {
                const char* sh = (const char*)g_wf
                    + ((size_t)((ntH * 8 + (tid2 >> 4)) * 32 + p) * 32) * 8
                    + (tid2 & 15) * 16;
                cpa16(ws2 + p * 4096 + tid2 * 16, sh);
                cpa16(ws2 + p * 4096 + 2048 + tid2 * 16, sh + (size_t)WF2 * 8);
                cpcommit();
            }

            float c[8][4];
#pragma unroll
            for (int i = 0; i < 8; i++)
#pragma unroll
                for (int q = 0; q < 4; q++) c[i][q] = 0.f;

            uint4 ah = g_af[((size_t)(t * 4 + w) * 32 + 0) * 32 + lane];
            uint4 al = g_af[((size_t)(t * 4 + w) * 32 + 0) * 32 + lane + AF4];

#pragma unroll 1
            for (int kc = 0; kc < 32; kc++) {
                if (kc < 31) cpwait<1>(); else cpwait<0>();
                asm volatile("bar.sync 6, 128;" ::: "memory");
                uint4 ahn, aln;
                if (kc + 1 < 32) {
                    ahn = g_af[((size_t)(t * 4 + w) * 32 + kc + 1) * 32 + lane];
                    aln = g_af[((size_t)(t * 4 + w) * 32 + kc + 1) * 32 + lane + AF4];
                }
                const uint2* wh = (const uint2*)(ws2 + (kc & 1) * 4096);
                const uint2* wl = (const uint2*)(ws2 + (kc & 1) * 4096 + 2048);
#pragma unroll
                for (int nfi = 0; nfi < 8; nfi++) {
                    uint2 h = wh[nfi * 32 + lane];
                    uint2 l = wl[nfi * 32 + lane];
                    mma16816(c[nfi], ah, h.x, h.y);
                    mma16816(c[nfi], al, h.x, h.y);
                    mma16816(c[nfi], ah, l.x, l.y);
                }
                asm volatile("bar.sync 6, 128;" ::: "memory");
                if (kc + 2 < 32) {
                    const char* sh = (const char*)g_wf
                        + ((size_t)((ntH * 8 + (tid2 >> 4)) * 32 + kc + 2) * 32) * 8
                        + (tid2 & 15) * 16;
                    cpa16(ws2 + (kc & 1) * 4096 + tid2 * 16, sh);
                    cpa16(ws2 + (kc & 1) * 4096 + 2048 + tid2 * 16, sh + (size_t)WF2 * 8);
                    cpcommit();
                }
                ah = ahn; al = aln;
            }

            // epilogue: scattered fp32 stores into g_xp[t][n][b]
#pragma unroll
            for (int nfi = 0; nfi < 8; nfi++) {
                int n = ntH * 64 + nfi * 8 + tc2;
                float* p = g_xp + ((size_t)t * G4 + n) * Bq + 16 * w + gr;
                p[0] = c[nfi][0];
                p[64] = c[nfi][1];
                p[8] = c[nfi][2];
                p[72] = c[nfi][3];
            }
            // every lane releases its own stores: 32 tiles * 128 lanes = 4096
            {
                unsigned old;
                asm volatile("atom.release.gpu.add.u32 %0, [%1], 1;"
                             : "=r"(old) : "l"(&g_td[t]) : "memory");
            }
        }
    }
}

extern "C" void kernel_launch(void* const* d_in, const int* in_sizes, int n_in,
                              void* d_out, int out_size) {
    const float* x   = (const float*)d_in[0];   // [512,64,512]
    const float* Wih = (const float*)d_in[1];   // [2048,512]
    const float* Whh = (const float*)d_in[2];   // [2048,512]
    const float* bih = (const float*)d_in[3];   // [2048]
    const float* bhh = (const float*)d_in[4];   // [2048]
    float* out = (float*)d_out;                 // [512,64,512]

    cudaFuncSetAttribute(lstm_rec, cudaFuncAttributeMaxDynamicSharedMemorySize, REC_SMEM);

    conv_a<<<8192, 256>>>(x);
    conv_w<<<1024, 256>>>(Wih);
    lstm_rec<<<128, 640, REC_SMEM>>>(Whh, bih, bhh, out);
}

// round 14
// speedup vs baseline: 1.3972x; 1.3972x over previous
#include <cuda_runtime.h>
#include <cuda_bf16.h>
#include <math.h>

// LSTM: T=512, B=64, I=H=512.  out[t,b,h] = h_t.
// conv_a/conv_w: split-bf16 fragments (R8, unchanged).
// lstm_rec (640 thr): warps 0-15 = persistent HMMA recurrence (R13, proven);
//   warps 16-19 = independent-warp GEMM sub-unit (R14: no smem, no barriers,
//   W fragments via __ldg; unit's ntH is fixed -> W slice L1-resident).

#define Tq 512
#define Bq 64
#define Hq 512
#define G4 2048
#define AF4 2097152u
#define WF2 262144u

typedef unsigned long long ull;

__device__ float g_xp[(size_t)Tq * G4 * Bq];        // x_proj scratch (no bias)
__device__ unsigned g_cnt[4 * 32];                  // per-group step counters
__device__ unsigned g_td[Tq];                       // per-t x_proj progress (4096 = done)
__device__ unsigned g_fin;                          // global finish counter
__device__ uint4 g_af[2 * AF4];                     // A frags hi|lo
__device__ uint2 g_wf[2 * WF2];                     // W_ih frags hi|lo
__device__ uint4 g_hf[2 * 8192];                    // h frags [par][hi|lo][bq][kc][lane]

__device__ __forceinline__ void cpa16(void* s, const void* g) {
    unsigned sa = (unsigned)__cvta_generic_to_shared(s);
    asm volatile("cp.async.cg.shared.global [%0], [%1], 16;" :: "r"(sa), "l"(g));
}
__device__ __forceinline__ void cpcommit() { asm volatile("cp.async.commit_group;"); }
template <int N> __device__ __forceinline__ void cpwait() {
    asm volatile("cp.async.wait_group %0;" :: "n"(N));
}
__device__ __forceinline__ float sigf(float x) {
    return __fdividef(1.f, 1.f + __expf(-x));
}
__device__ __forceinline__ float tanhx(float x) {
    return __fdividef(2.f, 1.f + __expf(-2.f * x)) - 1.f;
}
__device__ __forceinline__ void split2(float2 v, unsigned& hi, unsigned& lo) {
    __nv_bfloat16 hx = __float2bfloat16(v.x);
    __nv_bfloat16 hy = __float2bfloat16(v.y);
    __nv_bfloat16 lx = __float2bfloat16(v.x - __bfloat162float(hx));
    __nv_bfloat16 ly = __float2bfloat16(v.y - __bfloat162float(hy));
    hi = (unsigned)__bfloat16_as_ushort(hx) | ((unsigned)__bfloat16_as_ushort(hy) << 16);
    lo = (unsigned)__bfloat16_as_ushort(lx) | ((unsigned)__bfloat16_as_ushort(ly) << 16);
}
__device__ __forceinline__ void mma16816(float* c, uint4 a, unsigned b0, unsigned b1) {
    asm volatile(
        "mma.sync.aligned.m16n8k16.row.col.f32.bf16.bf16.f32 "
        "{%0,%1,%2,%3},{%4,%5,%6,%7},{%8,%9},{%0,%1,%2,%3};"
        : "+f"(c[0]), "+f"(c[1]), "+f"(c[2]), "+f"(c[3])
        : "r"(a.x), "r"(a.y), "r"(a.z), "r"(a.w), "r"(b0), "r"(b1));
}

__global__ __launch_bounds__(256) void conv_a(const float* __restrict__ x) {
    unsigned idx = blockIdx.x * 256 + threadIdx.x;
    int lane = idx & 31;
    int kc = (idx >> 5) & 31;
    int mf = idx >> 10;
    int gr = lane >> 2, tc = (lane & 3) * 2;
    const float* base = x + (size_t)(mf * 16 + gr) * 512 + kc * 16 + tc;
    float2 r0 = *(const float2*)(base);
    float2 r1 = *(const float2*)(base + 8);
    float2 r2 = *(const float2*)(base + 8 * 512);
    float2 r3 = *(const float2*)(base + 8 * 512 + 8);
    uint4 hi, lo;
    split2(r0, hi.x, lo.x);
    split2(r2, hi.y, lo.y);
    split2(r1, hi.z, lo.z);
    split2(r3, hi.w, lo.w);
    unsigned o = (mf * 32 + kc) * 32 + lane;
    g_af[o] = hi;
    g_af[o + AF4] = lo;
}

__global__ __launch_bounds__(256) void conv_w(const float* __restrict__ W) {
    unsigned idx = blockIdx.x * 256 + threadIdx.x;
    int lane = idx & 31;
    int kc = (idx >> 5) & 31;
    int nf = idx >> 10;
    int gr = lane >> 2, tc = (lane & 3) * 2;
    const float* base = W + (size_t)(nf * 8 + gr) * 512 + kc * 16 + tc;
    float2 r0 = *(const float2*)(base);
    float2 r1 = *(const float2*)(base + 8);
    uint2 hi, lo;
    split2(r0, hi.x, lo.x);
    split2(r1, hi.y, lo.y);
    unsigned o = (nf * 32 + kc) * 32 + lane;
    g_wf[o] = hi;
    g_wf[o + WF2] = lo;
}

// ---------------------------------------------------------------------------
// smem layout
// ---------------------------------------------------------------------------
#define OFF_WF_LO 65536
#define OFF_HF    131072
#define OFF_HF_LO 147456
#define OFF_PEX   163840      // [32 rows][68] f32 = 8704
#define OFF_HO    172544      // [16][16] f32 = 1024
#define OFF_HBL   173568      // [16][17] u32 = 1088
#define OFF_BS    174656      // 64 f32 = 256
#define REC_SMEM  174912

__global__ __launch_bounds__(640, 1) void lstm_rec(
    const float* __restrict__ Whh, const float* __restrict__ bih,
    const float* __restrict__ bhh, float* __restrict__ out)
{
    extern __shared__ __align__(16) char smc[];
    uint2* wfHI = (uint2*)(smc);
    uint2* wfLO = (uint2*)(smc + OFF_WF_LO);
    uint4* hfHI = (uint4*)(smc + OFF_HF);
    uint4* hfLO = (uint4*)(smc + OFF_HF_LO);
    float* pex = (float*)(smc + OFF_PEX);
    float* ho = (float*)(smc + OFF_HO);
    unsigned* hbl = (unsigned*)(smc + OFF_HBL);
    float* bsm = (float*)(smc + OFF_BS);

    const int tid = threadIdx.x;
    const int bq = blockIdx.x >> 5;
    const int hg = blockIdx.x & 31;
    const int b0 = bq * 16;
    const int hc0 = hg * 16;
    unsigned* cnt = &g_cnt[bq * 32];

    if (tid < 512) {
        // ================= recurrence warps (0..15) — R13, proven =========
        const int warp = tid >> 5;
        const int lane = tid & 31;
        const int eb = tid & 15;
        const int ehcl = (tid >> 4) & 15;
        const int nf = warp & 7;
        const int kh = warp >> 3;

        for (int idx = tid; idx < 8192; idx += 512) {
            int l = idx & 31, nfi = (idx >> 5) & 7, kc = idx >> 8;
            int gr = l >> 2, tc2 = (l & 3) * 2;
            int c = nfi * 8 + gr;
            int grow = (c & 3) * 512 + hc0 + (c >> 2);
            const float* wb = Whh + (size_t)grow * 512 + kc * 16 + tc2;
            float2 r0 = *(const float2*)wb;
            float2 r1 = *(const float2*)(wb + 8);
            unsigned h0, l0, h1, l1;
            split2(r0, h0, l0);
            split2(r1, h1, l1);
            wfHI[(kc * 8 + nfi) * 32 + l] = make_uint2(h0, h1);
            wfLO[(kc * 8 + nfi) * 32 + l] = make_uint2(l0, l1);
        }
        if (tid < 64)
            bsm[tid] = bih[(tid & 3) * 512 + hc0 + (tid >> 2)]
                     + bhh[(tid & 3) * 512 + hc0 + (tid >> 2)];
        asm volatile("bar.sync 7, 512;" ::: "memory");

        float cst = 0.f;

#pragma unroll 1
        for (int t = 0; t < Tq; t++) {
            if (tid == 0) {
                unsigned vt;
                asm volatile("ld.acquire.gpu.u32 %0, [%1];"
                             : "=r"(vt) : "l"(&g_td[t]) : "memory");
                if (t > 0) {
                    unsigned tgt = 32u * (unsigned)t;
                    unsigned v;
                    do {
                        asm volatile("ld.acquire.gpu.u32 %0, [%1];"
                                     : "=r"(v) : "l"(cnt) : "memory");
                    } while (v < tgt);
                }
                if (vt < 4096u) {
                    unsigned v;
                    do {
                        asm volatile("ld.acquire.gpu.u32 %0, [%1];"
                                     : "=r"(v) : "l"(&g_td[t]) : "memory");
                    } while (v < 4096u);
                }
            }
            asm volatile("bar.sync 7, 512;" ::: "memory");

            float xv0 = 0.f, xv1 = 0.f, xv2 = 0.f, xv3 = 0.f;
            if (tid < 256) {
                const float* xpt = g_xp + (size_t)t * (G4 * Bq)
                                 + (size_t)(hc0 + ehcl) * Bq + b0 + eb;
                xv0 = __ldcg(xpt + 0 * 512 * Bq);
                xv1 = __ldcg(xpt + 1 * 512 * Bq);
                xv2 = __ldcg(xpt + 2 * 512 * Bq);
                xv3 = __ldcg(xpt + 3 * 512 * Bq);
            }

            if (t > 0) {
                const char* gB = (const char*)g_hf + (size_t)(t & 1) * 131072
                               + bq * 16384 + kh * 8192;
                char* sH = (char*)hfHI + kh * 8192;
                char* sL = (char*)hfLO + kh * 8192;
                int l = tid & 255;
                cpa16(sH + l * 16, gB + l * 16);
                cpa16(sH + (l + 256) * 16, gB + (l + 256) * 16);
                cpa16(sL + l * 16, gB + 65536 + l * 16);
                cpa16(sL + (l + 256) * 16, gB + 65536 + (l + 256) * 16);
                cpcommit();
                cpwait<0>();
                asm volatile("bar.sync %0, 256;" :: "r"(1 + kh) : "memory");

                float cc[4] = { 0.f, 0.f, 0.f, 0.f };
#pragma unroll 4
                for (int kc16 = 0; kc16 < 16; kc16++) {
                    int kc = kh * 16 + kc16;
                    uint4 ah = hfHI[kc * 32 + lane];
                    uint4 al = hfLO[kc * 32 + lane];
                    uint2 wh = wfHI[(kc * 8 + nf) * 32 + lane];
                    uint2 wl = wfLO[(kc * 8 + nf) * 32 + lane];
                    mma16816(cc, ah, wh.x, wh.y);
                    mma16816(cc, al, wh.x, wh.y);
                    mma16816(cc, ah, wl.x, wl.y);
                }
                {
                    int gr = lane >> 2, tc2 = (lane & 3) * 2;
                    int col = nf * 8 + tc2;
                    *(float2*)&pex[(kh * 16 + gr) * 68 + col] = make_float2(cc[0], cc[1]);
                    *(float2*)&pex[(kh * 16 + gr + 8) * 68 + col] = make_float2(cc[2], cc[3]);
                }
                asm volatile("bar.sync 7, 512;" ::: "memory");
            }

            if (tid < 256) {
                float g0 = xv0 + bsm[ehcl * 4 + 0];
                float g1 = xv1 + bsm[ehcl * 4 + 1];
                float g2 = xv2 + bsm[ehcl * 4 + 2];
                float g3 = xv3 + bsm[ehcl * 4 + 3];
                if (t > 0) {
                    float4 p0 = *(const float4*)&pex[eb * 68 + ehcl * 4];
                    float4 p1 = *(const float4*)&pex[(16 + eb) * 68 + ehcl * 4];
                    g0 += p0.x + p1.x;
                    g1 += p0.y + p1.y;
                    g2 += p0.z + p1.z;
                    g3 += p0.w + p1.w;
                }
                float iv = sigf(g0);
                float fv = sigf(g1);
                float gv = tanhx(g2);
                float ov = sigf(g3);
                cst = fv * cst + iv * gv;
                float hv = ov * tanhx(cst);

                ho[eb * 16 + ehcl] = hv;
                {
                    __nv_bfloat16 hh = __float2bfloat16(hv);
                    __nv_bfloat16 hl = __float2bfloat16(hv - __bfloat162float(hh));
                    hbl[ehcl * 17 + eb] = (unsigned)__bfloat16_as_ushort(hh)
                                        | ((unsigned)__bfloat16_as_ushort(hl) << 16);
                }
                asm volatile("bar.sync 10, 256;" ::: "memory");

                if (tid < 32) {
                    if (t < Tq - 1) {
                        int gr = lane >> 2;
                        int k0 = (lane & 3) * 2;
                        unsigned x0 = hbl[k0 * 17 + gr],        x1 = hbl[(k0 + 1) * 17 + gr];
                        unsigned y0 = hbl[k0 * 17 + gr + 8],    y1 = hbl[(k0 + 1) * 17 + gr + 8];
                        unsigned z0 = hbl[(k0 + 8) * 17 + gr],  z1 = hbl[(k0 + 9) * 17 + gr];
                        unsigned w0 = hbl[(k0 + 8) * 17 + gr + 8], w1 = hbl[(k0 + 9) * 17 + gr + 8];
                        uint4 hi = make_uint4(__byte_perm(x0, x1, 0x5410),
                                              __byte_perm(y0, y1, 0x5410),
                                              __byte_perm(z0, z1, 0x5410),
                                              __byte_perm(w0, w1, 0x5410));
                        uint4 lo = make_uint4(__byte_perm(x0, x1, 0x7632),
                                              __byte_perm(y0, y1, 0x7632),
                                              __byte_perm(z0, z1, 0x7632),
                                              __byte_perm(w0, w1, 0x7632));
                        size_t base = (size_t)((t + 1) & 1) * 8192 + (bq * 32 + hg) * 32 + lane;
                        g_hf[base] = hi;
                        g_hf[base + 4096] = lo;
                        __syncwarp();
                        if (lane == 0) {
                            unsigned old;
                            asm volatile("atom.release.gpu.add.u32 %0, [%1], 1;"
                                         : "=r"(old) : "l"(cnt) : "memory");
                        }
                    }
                } else if (tid >= 64 && tid < 128) {
                    int row = (tid - 64) >> 2, f4 = (tid - 64) & 3;
                    float4 v = ((const float4*)(ho + row * 16))[f4];
                    *(float4*)&out[(size_t)t * (Bq * Hq) + (size_t)(b0 + row) * Hq
                                   + hc0 + f4 * 4] = v;
                }
            }
        }

        if (tid == 0) {
            unsigned old;
            asm volatile("atom.release.gpu.add.u32 %0, [%1], 1;"
                         : "=r"(old) : "l"(&g_fin) : "memory");
            if (old == 127u) {
                for (int i = 0; i < Tq; i++) ((volatile unsigned*)g_td)[i] = 0u;
                for (int i = 0; i < 4; i++) ((volatile unsigned*)g_cnt)[i * 32] = 0u;
                *((volatile unsigned*)&g_fin) = 0u;
            }
        }
    } else {
        // ========== GEMM sub-unit (warps 16..19) — independent warps ======
        // No smem, no barriers. W frags via __ldg (fixed ntH per unit ->
        // 128KB slice becomes L1/L2-resident after iteration 0).
        const int w = (tid >> 5) - 16;          // 0..3 -> 16 M-rows each
        const int lane = tid & 31;
        const int gr = lane >> 2, tc2 = (lane & 3) * 2;
        const int ntH = blockIdx.x & 31;        // fixed for this unit

#pragma unroll 1
        for (int j = blockIdx.x; j < Tq * 32; j += 128) {
            int t = j >> 5;

            float c[8][4];
#pragma unroll
            for (int i = 0; i < 8; i++)
#pragma unroll
                for (int q = 0; q < 4; q++) c[i][q] = 0.f;

            uint4 ah = g_af[((size_t)(t * 4 + w) * 32 + 0) * 32 + lane];
            uint4 al = g_af[((size_t)(t * 4 + w) * 32 + 0) * 32 + lane + AF4];

#pragma unroll 2
            for (int kc = 0; kc < 32; kc++) {
                uint4 ahn, aln;
                if (kc + 1 < 32) {
                    ahn = g_af[((size_t)(t * 4 + w) * 32 + kc + 1) * 32 + lane];
                    aln = g_af[((size_t)(t * 4 + w) * 32 + kc + 1) * 32 + lane + AF4];
                }
#pragma unroll
                for (int nfi = 0; nfi < 8; nfi++) {
                    unsigned wo = ((ntH * 8 + nfi) * 32 + kc) * 32 + lane;
                    uint2 h = __ldg(&g_wf[wo]);
                    uint2 l = __ldg(&g_wf[wo + WF2]);
                    mma16816(c[nfi], ah, h.x, h.y);
                    mma16816(c[nfi], al, h.x, h.y);
                    mma16816(c[nfi], ah, l.x, l.y);
                }
                ah = ahn; al = aln;
            }

            // epilogue: scattered fp32 stores into g_xp[t][n][b]
#pragma unroll
            for (int nfi = 0; nfi < 8; nfi++) {
                int n = ntH * 64 + nfi * 8 + tc2;
                float* p = g_xp + ((size_t)t * G4 + n) * Bq + 16 * w + gr;
                p[0] = c[nfi][0];
                p[64] = c[nfi][1];
                p[8] = c[nfi][2];
                p[72] = c[nfi][3];
            }
            // every lane releases its own stores: 32 tiles * 128 lanes = 4096
            {
                unsigned old;
                asm volatile("atom.release.gpu.add.u32 %0, [%1], 1;"
                             : "=r"(old) : "l"(&g_td[t]) : "memory");
            }
        }
    }
}

extern "C" void kernel_launch(void* const* d_in, const int* in_sizes, int n_in,
                              void* d_out, int out_size) {
    const float* x   = (const float*)d_in[0];   // [512,64,512]
    const float* Wih = (const float*)d_in[1];   // [2048,512]
    const float* Whh = (const float*)d_in[2];   // [2048,512]
    const float* bih = (const float*)d_in[3];   // [2048]
    const float* bhh = (const float*)d_in[4];   // [2048]
    float* out = (float*)d_out;                 // [512,64,512]

    cudaFuncSetAttribute(lstm_rec, cudaFuncAttributeMaxDynamicSharedMemorySize, REC_SMEM);

    conv_a<<<8192, 256>>>(x);
    conv_w<<<1024, 256>>>(Wih);
    lstm_rec<<<128, 640, REC_SMEM>>>(Whh, bih, bhh, out);
}